// round 12
// baseline (speedup 1.0000x reference)
#include <cuda_runtime.h>
#include <cstdint>
#include <cstddef>

#define SEQ     2048
#define BATCH   128
#define HID     256
#define THREADS 512
#define NCHUNK  16         // 16B h chunks per 64-col window
#define MF32    9          // chunks with f32 W in regs      (18 pairs/row)
#define MBF     3          // chunks with bf16 W in regs     ( 6 pairs/row)
#define MSM     4          // chunks with bf16 W in smem     ( 8 pairs/row)
#define WIN     288        // h window stride: 256B data + 32B pad (bank-disjoint q's)
#define HSTRIDE 1152       // bytes per h parity buffer (4 windows * 288)
#define WSMEMB  (MSM * THREADS * 16)   // 32 KB smem W (uint4 per chunk per thread)

typedef unsigned long long u64;

__device__ __forceinline__ u64 ffma2(u64 a, u64 b, u64 c) {
    u64 d;
    asm("fma.rn.f32x2 %0, %1, %2, %3;" : "=l"(d) : "l"(a), "l"(b), "l"(c));
    return d;
}
__device__ __forceinline__ u64 add2(u64 a, u64 b) {
    u64 d;
    asm("add.rn.f32x2 %0, %1, %2;" : "=l"(d) : "l"(a), "l"(b));
    return d;
}
__device__ __forceinline__ float lo32(u64 v) { return __uint_as_float((unsigned)(v & 0xffffffffu)); }
__device__ __forceinline__ float hi32(u64 v) { return __uint_as_float((unsigned)(v >> 32)); }
__device__ __forceinline__ float fast_tanh(float x) {
    float r;
    asm("tanh.approx.f32 %0, %1;" : "=f"(r) : "f"(x));
    return r;
}
__device__ __forceinline__ u64 packf(float a, float b) {
    return (u64)__float_as_uint(a) | ((u64)__float_as_uint(b) << 32);
}
// bf16x2: f_lo -> bits[15:0], f_hi -> bits[31:16]
__device__ __forceinline__ unsigned bfpack(float f_lo, float f_hi) {
    unsigned r;
    asm("cvt.rn.bf16x2.f32 %0, %1, %2;" : "=r"(r) : "f"(f_hi), "f"(f_lo));
    return r;
}
__device__ __forceinline__ u64 mk64(unsigned lo, unsigned hi) {
    u64 r;
    asm("mov.b64 %0, {%1, %2};" : "=l"(r) : "r"(lo), "r"(hi));
    return r;
}
// unpack u32 of 2 bf16 into a packed f32-pair u64 (2 ALU ops)
__device__ __forceinline__ u64 bf2f(unsigned v) {
    return mk64(v << 16, v & 0xffff0000u);
}
// h slot byte offset for hidden index j (32B pad every 64 floats)
__device__ __forceinline__ int hslot(int j) { return 4 * j + 32 * (j >> 6); }

// ---------------------------------------------------------------------------
// Persistent recurrence. One CTA per batch element, 512 threads.
// Thread tid: p = tid>>2 (rows p and p+128), q = tid&3 (cols [64q, 64q+64)).
// Each 16B h chunk read feeds 4 ffma2 (2 rows x 2 pairs) — h broadcast
// wavefronts halved vs 1-row layout. W in 3 tiers: f32 regs (chunks 0-8),
// bf16 regs (9-11), bf16 smem uint4 (12-15, both rows in one load).
// Row sums combine via shfl_xor(1)+shfl_xor(2). One __syncthreads per step.
// ---------------------------------------------------------------------------
__global__ void __launch_bounds__(THREADS, 1) rnn_kernel(
    const float* __restrict__ x,     const float* __restrict__ h0,
    const float* __restrict__ noise, const float* __restrict__ W_ih,
    const float* __restrict__ b_h,   const float* __restrict__ Whh,
    const float* __restrict__ Whb,   const void*  __restrict__ ctxp,
    float* __restrict__ h_out)
{
    extern __shared__ char smraw[];
    uint4*    Wsm4  = (uint4*)smraw;             // MSM*THREADS uint4 = 32 KB
    unsigned* Wsm32 = (unsigned*)smraw;
    char*     hbase = smraw + WSMEMB;            // 2 * HSTRIDE

    const int b   = blockIdx.x;
    const int tid = threadIdx.x;
    const int p   = tid >> 2;
    const int q   = tid & 3;
    const int r0  = p;
    const int r1  = p + 128;

    // context (int32/int64 low word, or float32 bit pattern)
    int iv = *(const int*)ctxp;
    const float ctx = (iv > -1000000 && iv < 1000000) ? (float)iv : *(const float*)ctxp;

    // ---- Build W_eff slices ----
    u64      Wreg[2 * 2 * MF32];   // [rs*18 + 2m(+1)]  f32 pairs, chunks 0..8
    unsigned Wbf [2 * 2 * MBF];    // [rs*6  + 2(m-9)(+1)] bf16 pairs, chunks 9..11
#pragma unroll
    for (int rs = 0; rs < 2; rs++) {
        const int r = rs ? r1 : r0;
        const float4* ph = (const float4*)(Whh + (size_t)r * HID + 64 * q);
        const float4* pb = (const float4*)(Whb + (size_t)r * HID + 64 * q);
#pragma unroll
        for (int m = 0; m < NCHUNK; m++) {
            float4 a4 = ph[m];
            float4 b4 = pb[m];
            float f0 = fmaf(ctx, b4.x, a4.x), f1 = fmaf(ctx, b4.y, a4.y);
            float f2 = fmaf(ctx, b4.z, a4.z), f3 = fmaf(ctx, b4.w, a4.w);
            if (m < MF32) {
                Wreg[rs * 2 * MF32 + 2 * m]     = packf(f0, f1);
                Wreg[rs * 2 * MF32 + 2 * m + 1] = packf(f2, f3);
            } else if (m < MF32 + MBF) {
                Wbf[rs * 2 * MBF + 2 * (m - MF32)]     = bfpack(f0, f1);
                Wbf[rs * 2 * MBF + 2 * (m - MF32) + 1] = bfpack(f2, f3);
            } else {
                // uint4 per chunk: {r0 pair0, r0 pair1, r1 pair0, r1 pair1}
                Wsm32[((m - MF32 - MBF) * THREADS + tid) * 4 + rs * 2 + 0] = bfpack(f0, f1);
                Wsm32[((m - MF32 - MBF) * THREADS + tid) * 4 + rs * 2 + 1] = bfpack(f2, f3);
            }
        }
    }

    const float win0 = W_ih[r0], win1 = W_ih[r1];
    const float bh0  = b_h[r0],  bh1  = b_h[r1];
    const int   sl0  = hslot(r0), sl1 = hslot(r1);

    if (q == 0) {
        *(float*)(hbase + sl0) = h0[b * HID + r0];
        *(float*)(hbase + sl1) = h0[b * HID + r1];
    }
    __syncthreads();

    const float* np = noise + (size_t)b * HID;
    float*       op = h_out + (size_t)b * SEQ * HID;
    const float* xp = x + b;

    for (int t = 0; t < SEQ; t++) {
        const int   par = t & 1;
        const char* hr  = hbase + par * HSTRIDE + q * WIN;     // read window
        char*       hw  = hbase + (par ^ 1) * HSTRIDE;         // write side

        // Prefetch streamed inputs early (consumed ~700 cycles later).
        float nz0 = 0.0f, nz1 = 0.0f;
        if (q == 0) {
            nz0 = __ldg(np + (size_t)t * (BATCH * HID) + r0);
            nz1 = __ldg(np + (size_t)t * (BATCH * HID) + r1);
        }
        const float xv = __ldg(xp + t * BATCH);

        u64 a00 = 0, a01 = 0, a10 = 0, a11 = 0;

        // f32-reg chunks 0..8: each h chunk feeds both rows.
#pragma unroll
        for (int m = 0; m < MF32; m++) {
            ulonglong2 hh = *(const ulonglong2*)(hr + m * 16);
            a00 = ffma2(Wreg[2 * m],                hh.x, a00);
            a01 = ffma2(Wreg[2 * m + 1],            hh.y, a01);
            a10 = ffma2(Wreg[2 * MF32 + 2 * m],     hh.x, a10);
            a11 = ffma2(Wreg[2 * MF32 + 2 * m + 1], hh.y, a11);
        }
        // bf16-reg chunks 9..11.
#pragma unroll
        for (int m = 0; m < MBF; m++) {
            ulonglong2 hh = *(const ulonglong2*)(hr + (MF32 + m) * 16);
            a00 = ffma2(bf2f(Wbf[2 * m]),               hh.x, a00);
            a01 = ffma2(bf2f(Wbf[2 * m + 1]),           hh.y, a01);
            a10 = ffma2(bf2f(Wbf[2 * MBF + 2 * m]),     hh.x, a10);
            a11 = ffma2(bf2f(Wbf[2 * MBF + 2 * m + 1]), hh.y, a11);
        }
        // bf16-smem chunks 12..15 (one uint4 load covers both rows).
#pragma unroll
        for (int m = 0; m < MSM; m++) {
            ulonglong2 hh = *(const ulonglong2*)(hr + (MF32 + MBF + m) * 16);
            uint4 w = Wsm4[m * THREADS + tid];
            a00 = ffma2(bf2f(w.x), hh.x, a00);
            a01 = ffma2(bf2f(w.y), hh.y, a01);
            a10 = ffma2(bf2f(w.z), hh.x, a10);
            a11 = ffma2(bf2f(w.w), hh.y, a11);
        }

        // Fold packed accumulators, combine 4 column quarters per row.
        u64 f0 = add2(a00, a01), f1 = add2(a10, a11);
        float s0 = lo32(f0) + hi32(f0);
        float s1 = lo32(f1) + hi32(f1);
        s0 += __shfl_xor_sync(0xffffffffu, s0, 1);
        s1 += __shfl_xor_sync(0xffffffffu, s1, 1);
        s0 += __shfl_xor_sync(0xffffffffu, s0, 2);
        s1 += __shfl_xor_sync(0xffffffffu, s1, 2);

        if (q == 0) {
            float hv0 = fast_tanh(fmaf(xv, win0, s0) + bh0) + nz0;
            float hv1 = fast_tanh(fmaf(xv, win1, s1) + bh1) + nz1;
            *(float*)(hw + sl0) = hv0;            // publish next h
            *(float*)(hw + sl1) = hv1;
            op[(size_t)t * HID + r0] = hv0;       // out[b, t, r] (streaming)
            op[(size_t)t * HID + r1] = hv1;
        }
        __syncthreads();
    }
}

// ---------------------------------------------------------------------------
// Output head: y[b,t] = sigmoid(<out[b,t,:], W[0,:]> + b[0]).
// One warp per (b,t); streaming read of 256 MB — measured 42.5us @ 81% DRAM.
// ---------------------------------------------------------------------------
__global__ void __launch_bounds__(256) head_kernel(
    const float* __restrict__ ho, const float* __restrict__ W,
    const float* __restrict__ bb, float* __restrict__ y)
{
    const int warp = (blockIdx.x * blockDim.x + threadIdx.x) >> 5;  // (b*SEQ + t)
    const int lane = threadIdx.x & 31;
    if (warp >= BATCH * SEQ) return;

    const float4* pv = (const float4*)(ho + (size_t)warp * HID);
    const float4* w4 = (const float4*)W;   // W[0,:] = first 256 floats

    float4 v0 = pv[lane],     v1 = pv[lane + 32];
    float4 w0 = w4[lane],     w1 = w4[lane + 32];

    float s = v0.x * w0.x;
    s = fmaf(v0.y, w0.y, s);  s = fmaf(v0.z, w0.z, s);  s = fmaf(v0.w, w0.w, s);
    s = fmaf(v1.x, w1.x, s);  s = fmaf(v1.y, w1.y, s);
    s = fmaf(v1.z, w1.z, s);  s = fmaf(v1.w, w1.w, s);

#pragma unroll
    for (int o = 16; o > 0; o >>= 1) s += __shfl_xor_sync(0xffffffffu, s, o);

    if (lane == 0)
        y[warp] = 1.0f / (1.0f + expf(-(s + bb[0])));
}

// ---------------------------------------------------------------------------
// Launch: inputs in metadata order
//   x, h0, noise, W_ih, W_hh, W_hh_bias, b_h, W, b, context
// Output: concat( y[:, :, 0] (BATCH,SEQ),  out (BATCH,SEQ,HID) ), fp32.
// ---------------------------------------------------------------------------
extern "C" void kernel_launch(void* const* d_in, const int* in_sizes, int n_in,
                              void* d_out, int out_size) {
    (void)in_sizes; (void)n_in; (void)out_size;
    const float* x    = (const float*)d_in[0];
    const float* h0   = (const float*)d_in[1];
    const float* nois = (const float*)d_in[2];
    const float* Wih  = (const float*)d_in[3];
    const float* Whh  = (const float*)d_in[4];
    const float* Whb  = (const float*)d_in[5];
    const float* bh   = (const float*)d_in[6];
    const float* W    = (const float*)d_in[7];
    const float* bb   = (const float*)d_in[8];
    const void*  ctx  = d_in[9];

    float* y  = (float*)d_out;
    float* ho = y + (size_t)BATCH * SEQ;

    const int smem_bytes = WSMEMB + 2 * HSTRIDE;   // 32 KB W + padded h buffers
    cudaFuncSetAttribute(rnn_kernel, cudaFuncAttributeMaxDynamicSharedMemorySize,
                         smem_bytes);

    rnn_kernel<<<BATCH, THREADS, smem_bytes>>>(x, h0, nois, Wih, bh,
                                               Whh, Whb, ctx, ho);

    const int nwarps  = BATCH * SEQ;                 // 262144
    const int nblocks = (nwarps * 32 + 255) / 256;   // 32768
    head_kernel<<<nblocks, 256>>>(ho, W, bb, y);
}